// round 1
// baseline (speedup 1.0000x reference)
#include <cuda_runtime.h>
#include <math.h>

#define EMBED 1024
#define BATCH 4
#define SEQ   2048

static constexpr int BM = 64, BN = 64, BK = 16;
static constexpr int PAD = 4;

// Scratch (device globals — no allocation inside kernel_launch)
__device__ float g_q[(size_t)BATCH * SEQ * EMBED];
__device__ float g_k[(size_t)BATCH * SEQ * EMBED];
__device__ float g_v[(size_t)BATCH * SEQ * EMBED];
__device__ float g_s[(size_t)BATCH * SEQ * SEQ];

// ---------------------------------------------------------------------------
// QKV projection: C[m,e] = sum_d x[m,d] * W[e,d]   (NT GEMM, M=8192,N=1024,K=1024)
// blockIdx.z selects {W_q->g_q, W_k->g_k, W_v->g_v}
// ---------------------------------------------------------------------------
__global__ __launch_bounds__(256, 2)
void qkv_kernel(const float* __restrict__ x, const float* __restrict__ Wq,
                const float* __restrict__ Wk, const float* __restrict__ Wv)
{
    __shared__ float As[BK][BM + PAD];
    __shared__ float Bs[BK][BN + PAD];

    const float* W;
    float* C;
    if (blockIdx.z == 0)      { W = Wq; C = g_q; }
    else if (blockIdx.z == 1) { W = Wk; C = g_k; }
    else                      { W = Wv; C = g_v; }

    const int m0 = blockIdx.x * BM, n0 = blockIdx.y * BN;
    const int tid = threadIdx.x;
    const int tr = (tid >> 4) * 4, tc = (tid & 15) * 4;
    const int lr = tid >> 2, lc = (tid & 3) * 4;

    const float* Ap = x + (size_t)(m0 + lr) * EMBED + lc;
    const float* Bp = W + (size_t)(n0 + lr) * EMBED + lc;

    float acc[4][4] = {};
    for (int k0 = 0; k0 < EMBED; k0 += BK) {
        float4 a = *reinterpret_cast<const float4*>(Ap + k0);
        float4 b = *reinterpret_cast<const float4*>(Bp + k0);
        As[lc + 0][lr] = a.x; As[lc + 1][lr] = a.y; As[lc + 2][lr] = a.z; As[lc + 3][lr] = a.w;
        Bs[lc + 0][lr] = b.x; Bs[lc + 1][lr] = b.y; Bs[lc + 2][lr] = b.z; Bs[lc + 3][lr] = b.w;
        __syncthreads();
#pragma unroll
        for (int kk = 0; kk < BK; kk++) {
            const float4 av = *reinterpret_cast<const float4*>(&As[kk][tr]);
            const float4 bv = *reinterpret_cast<const float4*>(&Bs[kk][tc]);
            const float a4[4] = {av.x, av.y, av.z, av.w};
            const float b4[4] = {bv.x, bv.y, bv.z, bv.w};
#pragma unroll
            for (int i = 0; i < 4; i++)
#pragma unroll
                for (int j = 0; j < 4; j++)
                    acc[i][j] = fmaf(a4[i], b4[j], acc[i][j]);
        }
        __syncthreads();
    }
#pragma unroll
    for (int i = 0; i < 4; i++) {
        float* c = C + (size_t)(m0 + tr + i) * EMBED + n0 + tc;
        c[0] = acc[i][0]; c[1] = acc[i][1]; c[2] = acc[i][2]; c[3] = acc[i][3];
    }
}

// ---------------------------------------------------------------------------
// Scores: S[b,q,k] = sum_d Q[b,q,d] * K[b,k,d]  (NT GEMM per batch, causal skip)
// Raw (unscaled) scores; scale folded into softmax.
// ---------------------------------------------------------------------------
__global__ __launch_bounds__(256, 2)
void scores_kernel()
{
    const int m0 = blockIdx.x * BM, n0 = blockIdx.y * BN;
    if (n0 > m0 + (BM - 1)) return;  // tile fully above the causal diagonal

    const int b = blockIdx.z;
    const float* Q = g_q + (size_t)b * SEQ * EMBED;
    const float* K = g_k + (size_t)b * SEQ * EMBED;
    float* C = g_s + (size_t)b * SEQ * SEQ;

    __shared__ float As[BK][BM + PAD];
    __shared__ float Bs[BK][BN + PAD];

    const int tid = threadIdx.x;
    const int tr = (tid >> 4) * 4, tc = (tid & 15) * 4;
    const int lr = tid >> 2, lc = (tid & 3) * 4;

    const float* Ap = Q + (size_t)(m0 + lr) * EMBED + lc;
    const float* Bp = K + (size_t)(n0 + lr) * EMBED + lc;

    float acc[4][4] = {};
    for (int k0 = 0; k0 < EMBED; k0 += BK) {
        float4 a = *reinterpret_cast<const float4*>(Ap + k0);
        float4 b = *reinterpret_cast<const float4*>(Bp + k0);
        As[lc + 0][lr] = a.x; As[lc + 1][lr] = a.y; As[lc + 2][lr] = a.z; As[lc + 3][lr] = a.w;
        Bs[lc + 0][lr] = b.x; Bs[lc + 1][lr] = b.y; Bs[lc + 2][lr] = b.z; Bs[lc + 3][lr] = b.w;
        __syncthreads();
#pragma unroll
        for (int kk = 0; kk < BK; kk++) {
            const float4 av = *reinterpret_cast<const float4*>(&As[kk][tr]);
            const float4 bv = *reinterpret_cast<const float4*>(&Bs[kk][tc]);
            const float a4[4] = {av.x, av.y, av.z, av.w};
            const float b4[4] = {bv.x, bv.y, bv.z, bv.w};
#pragma unroll
            for (int i = 0; i < 4; i++)
#pragma unroll
                for (int j = 0; j < 4; j++)
                    acc[i][j] = fmaf(a4[i], b4[j], acc[i][j]);
        }
        __syncthreads();
    }
#pragma unroll
    for (int i = 0; i < 4; i++) {
        float* c = C + (size_t)(m0 + tr + i) * SEQ + n0 + tc;
        c[0] = acc[i][0]; c[1] = acc[i][1]; c[2] = acc[i][2]; c[3] = acc[i][3];
    }
}

// ---------------------------------------------------------------------------
// Row softmax with causal truncation: row (b,q) has valid keys k in [0, q].
// Writes normalized probs for k<=q and zeros for k>q (so PV GEMM reads clean P).
// ---------------------------------------------------------------------------
__global__ __launch_bounds__(256)
void softmax_kernel()
{
    const int q = blockIdx.x, b = blockIdx.y;
    float* s = g_s + ((size_t)b * SEQ + q) * SEQ;
    const int tid = threadIdx.x;
    const float scale = 0.03125f;  // 1/sqrt(1024)

    __shared__ float red[8];

    float mx = -INFINITY;
    for (int k = tid; k <= q; k += 256) mx = fmaxf(mx, s[k]);
#pragma unroll
    for (int o = 16; o; o >>= 1) mx = fmaxf(mx, __shfl_xor_sync(0xffffffffu, mx, o));
    if ((tid & 31) == 0) red[tid >> 5] = mx;
    __syncthreads();
    float bmx = red[0];
#pragma unroll
    for (int w = 1; w < 8; w++) bmx = fmaxf(bmx, red[w]);
    __syncthreads();

    float sum = 0.f;
    for (int k = tid; k <= q; k += 256) {
        float e = __expf((s[k] - bmx) * scale);
        s[k] = e;
        sum += e;
    }
#pragma unroll
    for (int o = 16; o; o >>= 1) sum += __shfl_xor_sync(0xffffffffu, sum, o);
    if ((tid & 31) == 0) red[tid >> 5] = sum;
    __syncthreads();
    float bs = 0.f;
#pragma unroll
    for (int w = 0; w < 8; w++) bs += red[w];
    const float inv = 1.0f / bs;

    for (int k = tid; k <= q; k += 256) s[k] *= inv;
    for (int k = q + 1 + tid; k < SEQ; k += 256) s[k] = 0.f;
}

// ---------------------------------------------------------------------------
// PV: out[b,q,d] = sum_k P[b,q,k] * V[b,k,d]  (NN GEMM per batch,
// K-loop truncated to keys < m0+BM by causality; P is zero past the diagonal)
// ---------------------------------------------------------------------------
__global__ __launch_bounds__(256, 2)
void pv_kernel(float* __restrict__ out)
{
    const int b = blockIdx.z;
    const int m0 = blockIdx.x * BM, n0 = blockIdx.y * BN;
    const float* P = g_s + (size_t)b * SEQ * SEQ;
    const float* V = g_v + (size_t)b * SEQ * EMBED;
    float* C = out + (size_t)b * SEQ * EMBED;

    __shared__ float As[BK][BM + PAD];
    __shared__ float Bs[BK][BN + PAD];

    const int tid = threadIdx.x;
    const int tr = (tid >> 4) * 4, tc = (tid & 15) * 4;
    const int lr = tid >> 2, lc = (tid & 3) * 4;   // A tile loader (64x16)
    const int br = tid >> 4, bc = (tid & 15) * 4;  // B tile loader (16x64)

    float acc[4][4] = {};
    const int kend = m0 + BM;  // keys >= m0+BM have P == 0 for all rows in this tile
    for (int k0 = 0; k0 < kend; k0 += BK) {
        float4 a = *reinterpret_cast<const float4*>(&P[(size_t)(m0 + lr) * SEQ + k0 + lc]);
        As[lc + 0][lr] = a.x; As[lc + 1][lr] = a.y; As[lc + 2][lr] = a.z; As[lc + 3][lr] = a.w;
        float4 bv4 = *reinterpret_cast<const float4*>(&V[(size_t)(k0 + br) * EMBED + n0 + bc]);
        *reinterpret_cast<float4*>(&Bs[br][bc]) = bv4;
        __syncthreads();
#pragma unroll
        for (int kk = 0; kk < BK; kk++) {
            const float4 av = *reinterpret_cast<const float4*>(&As[kk][tr]);
            const float4 bv = *reinterpret_cast<const float4*>(&Bs[kk][tc]);
            const float a4[4] = {av.x, av.y, av.z, av.w};
            const float b4[4] = {bv.x, bv.y, bv.z, bv.w};
#pragma unroll
            for (int i = 0; i < 4; i++)
#pragma unroll
                for (int j = 0; j < 4; j++)
                    acc[i][j] = fmaf(a4[i], b4[j], acc[i][j]);
        }
        __syncthreads();
    }
#pragma unroll
    for (int i = 0; i < 4; i++) {
        float* c = C + (size_t)(m0 + tr + i) * EMBED + n0 + tc;
        c[0] = acc[i][0]; c[1] = acc[i][1]; c[2] = acc[i][2]; c[3] = acc[i][3];
    }
}

// ---------------------------------------------------------------------------
extern "C" void kernel_launch(void* const* d_in, const int* in_sizes, int n_in,
                              void* d_out, int out_size)
{
    const float* x  = (const float*)d_in[0];
    const float* Wq = (const float*)d_in[1];
    const float* Wk = (const float*)d_in[2];
    const float* Wv = (const float*)d_in[3];
    float* out = (float*)d_out;

    dim3 t(256);
    qkv_kernel<<<dim3((BATCH * SEQ) / BM, EMBED / BN, 3), t>>>(x, Wq, Wk, Wv);
    scores_kernel<<<dim3(SEQ / BM, SEQ / BN, BATCH), t>>>();
    softmax_kernel<<<dim3(SEQ, BATCH), t>>>();
    pv_kernel<<<dim3(SEQ / BM, EMBED / BN, BATCH), t>>>(out);
}

// round 3
// speedup vs baseline: 3.2645x; 3.2645x over previous
#include <cuda_runtime.h>
#include <cuda_bf16.h>
#include <cstdint>
#include <math.h>

#define EMBED 1024
#define BATCH 4
#define SEQ   2048
#define MTOT  (BATCH*SEQ)   // 8192

static constexpr int BM = 128, BN = 128, KC = 64;
static constexpr int SMEM_TOTAL = 2 * 32768;   // 2 bufs x (16KB A + 16KB B)

// ---------------- scratch (device globals; no runtime allocation) ----------------
__device__ __nv_bfloat16 g_xh[(size_t)MTOT * EMBED], g_xl[(size_t)MTOT * EMBED];
__device__ __nv_bfloat16 g_wh[3][(size_t)EMBED * EMBED], g_wl[3][(size_t)EMBED * EMBED];
__device__ __nv_bfloat16 g_qh[(size_t)MTOT * EMBED], g_ql[(size_t)MTOT * EMBED];
__device__ __nv_bfloat16 g_kh[(size_t)MTOT * EMBED], g_kl[(size_t)MTOT * EMBED];
__device__ __nv_bfloat16 g_vh[(size_t)MTOT * EMBED], g_vl[(size_t)MTOT * EMBED];
__device__ __nv_bfloat16 g_vth[(size_t)BATCH * EMBED * SEQ], g_vtl[(size_t)BATCH * EMBED * SEQ];
__device__ float         g_s[(size_t)BATCH * SEQ * SEQ];
__device__ __nv_bfloat16 g_ph[(size_t)BATCH * SEQ * SEQ], g_pl[(size_t)BATCH * SEQ * SEQ];

// ---------------- sm_80-compatible PTX helpers ----------------
static __device__ __forceinline__ uint32_t s2u(const void* p) {
    uint32_t a;
    asm("{ .reg .u64 t; cvta.to.shared.u64 t, %1; cvt.u32.u64 %0, t; }" : "=r"(a) : "l"(p));
    return a;
}
static __device__ __forceinline__ void cp16(uint32_t dst, const void* src) {
    asm volatile("cp.async.cg.shared.global [%0], [%1], 16;" :: "r"(dst), "l"(src));
}
static __device__ __forceinline__ void cpcommit() {
    asm volatile("cp.async.commit_group;" ::: "memory");
}
template<int N> static __device__ __forceinline__ void cpwait() {
    asm volatile("cp.async.wait_group %0;" :: "n"(N) : "memory");
}
static __device__ __forceinline__ void ldm4(uint32_t r[4], uint32_t a) {
    asm volatile("ldmatrix.sync.aligned.m8n8.x4.shared.b16 {%0,%1,%2,%3}, [%4];"
                 : "=r"(r[0]), "=r"(r[1]), "=r"(r[2]), "=r"(r[3]) : "r"(a));
}
static __device__ __forceinline__ void mma16816(float d[4], const uint32_t a[4],
                                                uint32_t b0, uint32_t b1) {
    asm volatile(
        "mma.sync.aligned.m16n8k16.row.col.f32.bf16.bf16.f32 "
        "{%0,%1,%2,%3}, {%4,%5,%6,%7}, {%8,%9}, {%0,%1,%2,%3};"
        : "+f"(d[0]), "+f"(d[1]), "+f"(d[2]), "+f"(d[3])
        : "r"(a[0]), "r"(a[1]), "r"(a[2]), "r"(a[3]), "r"(b0), "r"(b1));
}
static __device__ __forceinline__ uint32_t swz(uint32_t off) {
    return off ^ ((off >> 3) & 0x70);
}
static __device__ __forceinline__ void split2f(float fa, float fb, uint32_t& hh, uint32_t& ll) {
    __nv_bfloat16 ha = __float2bfloat16(fa), hb = __float2bfloat16(fb);
    __nv_bfloat16 la = __float2bfloat16(fa - __bfloat162float(ha));
    __nv_bfloat16 lb = __float2bfloat16(fb - __bfloat162float(hb));
    hh = (uint32_t)__bfloat16_as_ushort(ha) | ((uint32_t)__bfloat16_as_ushort(hb) << 16);
    ll = (uint32_t)__bfloat16_as_ushort(la) | ((uint32_t)__bfloat16_as_ushort(lb) << 16);
}

// ---------------- GEMM core: C(128x128) = sum_p A[p](128xK) * B[p](128xK)^T ----------------
struct Frag { float a[2][8][4]; };   // [m-subtile][n-tile][regs]

static __device__ __forceinline__ void issue_chunk(const __nv_bfloat16* Ap,
                                                   const __nv_bfloat16* Bp,
                                                   int lda, int ldb, int kc,
                                                   uint32_t sb, int buf)
{
    const int t = threadIdx.x;
    const uint32_t abase = sb + buf * 32768;
    const uint32_t bbase = abase + 16384;
#pragma unroll
    for (int i = 0; i < 4; i++) {
        int u = t + i * 256;
        int row = u >> 3, k16 = u & 7;
        const __nv_bfloat16* ga = Ap + (size_t)row * lda + kc + k16 * 8;
        const __nv_bfloat16* gb = Bp + (size_t)row * ldb + kc + k16 * 8;
        uint32_t sw = swz(row * 128 + k16 * 16);
        cp16(abase + sw, ga);
        cp16(bbase + sw, gb);
    }
    cpcommit();
}

static __device__ __forceinline__ void gemm_core(Frag& f,
        const __nv_bfloat16* A0, const __nv_bfloat16* A1, const __nv_bfloat16* A2,
        const __nv_bfloat16* B0, const __nv_bfloat16* B1, const __nv_bfloat16* B2,
        int lda, int ldb, int kpart, uint32_t sb)
{
    const int cpp = kpart >> 6;
    const int total = cpp * 3;
    const int lane = threadIdx.x & 31, wid = threadIdx.x >> 5;
    const int wm = wid >> 1, wn = wid & 1;

    const int rowA = wm * 32 + (lane & 15);
    const int kbA  = ((lane >> 4) & 1) * 16;
    const int rowB = wn * 64 + (lane & 7) + ((lane >> 4) << 3);
    const int kbB  = ((lane >> 3) & 1) * 16;

#pragma unroll
    for (int mt = 0; mt < 2; mt++)
#pragma unroll
        for (int nt = 0; nt < 8; nt++)
#pragma unroll
            for (int r = 0; r < 4; r++) f.a[mt][nt][r] = 0.f;

    issue_chunk(A0, B0, lda, ldb, 0, sb, 0);

    for (int g = 0; g < total; g++) {
        if (g + 1 < total) {
            int g1 = g + 1;
            int p = g1 / cpp;
            int kc = (g1 - p * cpp) * KC;
            const __nv_bfloat16* Ap = (p == 0) ? A0 : (p == 1 ? A1 : A2);
            const __nv_bfloat16* Bp = (p == 0) ? B0 : (p == 1 ? B1 : B2);
            issue_chunk(Ap, Bp, lda, ldb, kc, sb, g1 & 1);
            cpwait<1>();
        } else {
            cpwait<0>();
        }
        __syncthreads();

        const uint32_t abase = sb + (g & 1) * 32768;
        const uint32_t bbase = abase + 16384;
#pragma unroll
        for (int kk = 0; kk < 4; kk++) {
            uint32_t af[2][4], bf[4][4];
#pragma unroll
            for (int mt = 0; mt < 2; mt++)
                ldm4(af[mt], abase + swz((rowA + mt * 16) * 128 + kk * 32 + kbA));
#pragma unroll
            for (int pr = 0; pr < 4; pr++)
                ldm4(bf[pr], bbase + swz((rowB + pr * 16) * 128 + kk * 32 + kbB));
#pragma unroll
            for (int mt = 0; mt < 2; mt++)
#pragma unroll
                for (int nt = 0; nt < 8; nt++)
                    mma16816(f.a[mt][nt], af[mt], bf[nt >> 1][(nt & 1) * 2],
                             bf[nt >> 1][(nt & 1) * 2 + 1]);
        }
        __syncthreads();
    }
}

// ---------------- split kernels ----------------
__global__ __launch_bounds__(256) void split_x_kernel(const float* __restrict__ src)
{
    size_t i = ((size_t)blockIdx.x * 256 + threadIdx.x) * 4;
    float4 v = *reinterpret_cast<const float4*>(src + i);
    uint32_t h0, l0, h1, l1;
    split2f(v.x, v.y, h0, l0);
    split2f(v.z, v.w, h1, l1);
    *reinterpret_cast<uint2*>(g_xh + i) = make_uint2(h0, h1);
    *reinterpret_cast<uint2*>(g_xl + i) = make_uint2(l0, l1);
}
__global__ __launch_bounds__(256) void split_w_kernel(const float* __restrict__ src, int z)
{
    size_t i = ((size_t)blockIdx.x * 256 + threadIdx.x) * 4;
    float4 v = *reinterpret_cast<const float4*>(src + i);
    uint32_t h0, l0, h1, l1;
    split2f(v.x, v.y, h0, l0);
    split2f(v.z, v.w, h1, l1);
    *reinterpret_cast<uint2*>(&g_wh[z][i]) = make_uint2(h0, h1);
    *reinterpret_cast<uint2*>(&g_wl[z][i]) = make_uint2(l0, l1);
}

// ---------------- stage 1: QKV projection ----------------
__global__ __launch_bounds__(256) void qkv_gemm()
{
    extern __shared__ char sm[];
    const uint32_t sb = s2u(sm);
    const int z = blockIdx.z;
    const int m0 = blockIdx.x * BM, n0 = blockIdx.y * BN;

    const __nv_bfloat16* Ah = g_xh + (size_t)m0 * EMBED;
    const __nv_bfloat16* Al = g_xl + (size_t)m0 * EMBED;
    const __nv_bfloat16* Bh = g_wh[z] + (size_t)n0 * EMBED;
    const __nv_bfloat16* Bl = g_wl[z] + (size_t)n0 * EMBED;

    Frag f;
    gemm_core(f, Ah, Ah, Al, Bh, Bl, Bh, EMBED, EMBED, EMBED, sb);

    __nv_bfloat16* H = (z == 0) ? g_qh : (z == 1 ? g_kh : g_vh);
    __nv_bfloat16* L = (z == 0) ? g_ql : (z == 1 ? g_kl : g_vl);

    const int lane = threadIdx.x & 31, wid = threadIdx.x >> 5;
    const int wm = wid >> 1, wn = wid & 1;
    const int mb = m0 + wm * 32 + (lane >> 2);
    const int nb = n0 + wn * 64 + (lane & 3) * 2;
#pragma unroll
    for (int mt = 0; mt < 2; mt++)
#pragma unroll
        for (int nt = 0; nt < 8; nt++) {
            const int r0 = mb + mt * 16;
            const int c = nb + nt * 8;
            uint32_t hh, ll;
            split2f(f.a[mt][nt][0], f.a[mt][nt][1], hh, ll);
            *reinterpret_cast<uint32_t*>(H + (size_t)r0 * EMBED + c) = hh;
            *reinterpret_cast<uint32_t*>(L + (size_t)r0 * EMBED + c) = ll;
            split2f(f.a[mt][nt][2], f.a[mt][nt][3], hh, ll);
            *reinterpret_cast<uint32_t*>(H + (size_t)(r0 + 8) * EMBED + c) = hh;
            *reinterpret_cast<uint32_t*>(L + (size_t)(r0 + 8) * EMBED + c) = ll;
        }
}

// ---------------- V transpose: [b,s,e] -> [b,e,s] (both h and l) ----------------
__global__ __launch_bounds__(256) void transpose_v()
{
    __shared__ __nv_bfloat16 th[32][33], tl[32][33];
    const int b = blockIdx.z;
    const int s0 = blockIdx.x * 32, n0 = blockIdx.y * 32;
    const int tx = threadIdx.x, ty = threadIdx.y;  // 32 x 8
#pragma unroll
    for (int i = 0; i < 4; i++) {
        size_t idx = ((size_t)b * SEQ + s0 + ty + i * 8) * EMBED + n0 + tx;
        th[ty + i * 8][tx] = g_vh[idx];
        tl[ty + i * 8][tx] = g_vl[idx];
    }
    __syncthreads();
#pragma unroll
    for (int i = 0; i < 4; i++) {
        size_t idx = ((size_t)b * EMBED + n0 + ty + i * 8) * SEQ + s0 + tx;
        g_vth[idx] = th[tx][ty + i * 8];
        g_vtl[idx] = tl[tx][ty + i * 8];
    }
}

// ---------------- stage 2: causal scores ----------------
__global__ __launch_bounds__(256) void scores_gemm()
{
    if (blockIdx.y > blockIdx.x) return;  // tile fully above diagonal
    extern __shared__ char sm[];
    const uint32_t sb = s2u(sm);
    const int b = blockIdx.z;
    const int m0 = blockIdx.x * BM, n0 = blockIdx.y * BN;
    const size_t ro = (size_t)b * SEQ;

    const __nv_bfloat16* Ah = g_qh + (ro + m0) * EMBED;
    const __nv_bfloat16* Al = g_ql + (ro + m0) * EMBED;
    const __nv_bfloat16* Bh = g_kh + (ro + n0) * EMBED;
    const __nv_bfloat16* Bl = g_kl + (ro + n0) * EMBED;

    Frag f;
    gemm_core(f, Ah, Ah, Al, Bh, Bl, Bh, EMBED, EMBED, EMBED, sb);

    const int lane = threadIdx.x & 31, wid = threadIdx.x >> 5;
    const int wm = wid >> 1, wn = wid & 1;
    const int mb = m0 + wm * 32 + (lane >> 2);
    const int nb = n0 + wn * 64 + (lane & 3) * 2;
    float* S = g_s + (size_t)b * SEQ * SEQ;
#pragma unroll
    for (int mt = 0; mt < 2; mt++)
#pragma unroll
        for (int nt = 0; nt < 8; nt++) {
            const int r0 = mb + mt * 16;
            const int c = nb + nt * 8;
            *reinterpret_cast<float2*>(S + (size_t)r0 * SEQ + c) =
                make_float2(f.a[mt][nt][0], f.a[mt][nt][1]);
            *reinterpret_cast<float2*>(S + (size_t)(r0 + 8) * SEQ + c) =
                make_float2(f.a[mt][nt][2], f.a[mt][nt][3]);
        }
}

// ---------------- softmax (fp32 in, split-bf16 P out) ----------------
__global__ __launch_bounds__(256) void softmax_kernel()
{
    const int q = blockIdx.x, b = blockIdx.y;
    float* s = g_s + ((size_t)b * SEQ + q) * SEQ;
    __nv_bfloat16* ph = g_ph + ((size_t)b * SEQ + q) * SEQ;
    __nv_bfloat16* pl = g_pl + ((size_t)b * SEQ + q) * SEQ;
    const int tid = threadIdx.x;
    const float scale = 0.03125f;  // 1/sqrt(1024)
    __shared__ float red[8];

    float mx = -INFINITY;
    for (int k = tid; k <= q; k += 256) mx = fmaxf(mx, s[k]);
#pragma unroll
    for (int o = 16; o; o >>= 1) mx = fmaxf(mx, __shfl_xor_sync(0xffffffffu, mx, o));
    if ((tid & 31) == 0) red[tid >> 5] = mx;
    __syncthreads();
    float bmx = red[0];
#pragma unroll
    for (int w = 1; w < 8; w++) bmx = fmaxf(bmx, red[w]);
    __syncthreads();

    float sum = 0.f;
    for (int k = tid; k <= q; k += 256) {
        float e = __expf((s[k] - bmx) * scale);
        s[k] = e;
        sum += e;
    }
#pragma unroll
    for (int o = 16; o; o >>= 1) sum += __shfl_xor_sync(0xffffffffu, sum, o);
    if ((tid & 31) == 0) red[tid >> 5] = sum;
    __syncthreads();
    float bs = 0.f;
#pragma unroll
    for (int w = 0; w < 8; w++) bs += red[w];
    const float inv = 1.0f / bs;

    const __nv_bfloat16 z = __float2bfloat16(0.0f);
    for (int k = tid; k <= q; k += 256) {
        float p = s[k] * inv;
        __nv_bfloat16 h = __float2bfloat16(p);
        __nv_bfloat16 l = __float2bfloat16(p - __bfloat162float(h));
        ph[k] = h; pl[k] = l;
    }
    for (int k = q + 1 + tid; k < SEQ; k += 256) { ph[k] = z; pl[k] = z; }
}

// ---------------- stage 3: P @ V ----------------
__global__ __launch_bounds__(256) void pv_gemm(float* __restrict__ out)
{
    extern __shared__ char sm[];
    const uint32_t sb = s2u(sm);
    const int b = blockIdx.z;
    const int m0 = blockIdx.x * BM, n0 = blockIdx.y * BN;

    const __nv_bfloat16* Ah = g_ph + ((size_t)b * SEQ + m0) * SEQ;
    const __nv_bfloat16* Al = g_pl + ((size_t)b * SEQ + m0) * SEQ;
    const __nv_bfloat16* Bh = g_vth + ((size_t)b * EMBED + n0) * SEQ;
    const __nv_bfloat16* Bl = g_vtl + ((size_t)b * EMBED + n0) * SEQ;

    const int kend = m0 + BM;  // P is zero beyond the diagonal tile
    Frag f;
    gemm_core(f, Ah, Ah, Al, Bh, Bl, Bh, SEQ, SEQ, kend, sb);

    const int lane = threadIdx.x & 31, wid = threadIdx.x >> 5;
    const int wm = wid >> 1, wn = wid & 1;
    const int mb = m0 + wm * 32 + (lane >> 2);
    const int nb = n0 + wn * 64 + (lane & 3) * 2;
    float* C = out + (size_t)b * SEQ * EMBED;
#pragma unroll
    for (int mt = 0; mt < 2; mt++)
#pragma unroll
        for (int nt = 0; nt < 8; nt++) {
            const int r0 = mb + mt * 16;
            const int c = nb + nt * 8;
            *reinterpret_cast<float2*>(C + (size_t)r0 * EMBED + c) =
                make_float2(f.a[mt][nt][0], f.a[mt][nt][1]);
            *reinterpret_cast<float2*>(C + (size_t)(r0 + 8) * EMBED + c) =
                make_float2(f.a[mt][nt][2], f.a[mt][nt][3]);
        }
}

// ---------------- launch ----------------
extern "C" void kernel_launch(void* const* d_in, const int* in_sizes, int n_in,
                              void* d_out, int out_size)
{
    const float* x  = (const float*)d_in[0];
    const float* Wq = (const float*)d_in[1];
    const float* Wk = (const float*)d_in[2];
    const float* Wv = (const float*)d_in[3];
    float* out = (float*)d_out;

    cudaFuncSetAttribute(qkv_gemm,    cudaFuncAttributeMaxDynamicSharedMemorySize, SMEM_TOTAL);
    cudaFuncSetAttribute(scores_gemm, cudaFuncAttributeMaxDynamicSharedMemorySize, SMEM_TOTAL);
    cudaFuncSetAttribute(pv_gemm,     cudaFuncAttributeMaxDynamicSharedMemorySize, SMEM_TOTAL);

    split_x_kernel<<<(MTOT * EMBED / 4) / 256, 256>>>(x);
    split_w_kernel<<<(EMBED * EMBED / 4) / 256, 256>>>(Wq, 0);
    split_w_kernel<<<(EMBED * EMBED / 4) / 256, 256>>>(Wk, 1);
    split_w_kernel<<<(EMBED * EMBED / 4) / 256, 256>>>(Wv, 2);

    qkv_gemm<<<dim3(MTOT / BM, EMBED / BN, 3), 256, SMEM_TOTAL>>>();
    transpose_v<<<dim3(SEQ / 32, EMBED / 32, BATCH), dim3(32, 8)>>>();
    scores_gemm<<<dim3(SEQ / BM, SEQ / BN, BATCH), 256, SMEM_TOTAL>>>();
    softmax_kernel<<<dim3(SEQ, BATCH), 256>>>();
    pv_gemm<<<dim3(SEQ / BM, EMBED / BN, BATCH), 256, SMEM_TOTAL>>>(out);
}